// round 6
// baseline (speedup 1.0000x reference)
#include <cuda_runtime.h>

#define NN 100000
#define NE 1600000
#define FI 256
#define HD 32
#define AD 64
#define PD 512

// Scratch: __device__ globals referenced DIRECTLY by kernels.
__device__ float g_buf1[NN * HD];
__device__ float g_buf2[NN * HD];
__device__ float g_deg[NN];
__device__ float g_dinv[NN];

// ---------------------------------------------------------------------------
__global__ void k_zerodeg() {
    int i = blockIdx.x * blockDim.x + threadIdx.x;
    if (i < NN) g_deg[i] = 0.0f;
}

// edge_index is int32 (JAX demotes int64 -> int32 without x64 mode).
__global__ void k_deg(const int* __restrict__ dst) {
    int i = blockIdx.x * blockDim.x + threadIdx.x;
    if (i < NE) atomicAdd(&g_deg[dst[i]], 1.0f);
}

__global__ void k_dinv() {
    int i = blockIdx.x * blockDim.x + threadIdx.x;
    if (i < NN) g_dinv[i] = rsqrtf(g_deg[i] + 1.0f);  // +1 = self loop
}

// ---------------------------------------------------------------------------
// GEMM1: g_buf1 = features @ W1   ([100k,256] x [256,32])
// W1 in 32KB static smem; features streamed via float4 warp broadcasts.
// ---------------------------------------------------------------------------
__global__ void __launch_bounds__(256) k_gemm1(const float* __restrict__ feat,
                                               const float* __restrict__ W1) {
    __shared__ float sW[FI * HD];  // 8192 floats = 32KB
    int t = threadIdx.x;
#pragma unroll
    for (int i = 0; i < FI * HD / 256; i++) sW[t + i * 256] = W1[t + i * 256];
    __syncthreads();

    int c = t & 31, rg = t >> 5;  // rg constant within a warp
    long long row0 = (long long)blockIdx.x * 32;
    const float* f0 = feat + (row0 + rg) * FI;

    float a0 = 0.f, a1 = 0.f, a2 = 0.f, a3 = 0.f;
#pragma unroll 4
    for (int k = 0; k < FI; k += 4) {
        float4 fa = __ldg((const float4*)(f0 + k));
        float4 fb = __ldg((const float4*)(f0 + 8 * FI + k));
        float4 fc = __ldg((const float4*)(f0 + 16 * FI + k));
        float4 fd = __ldg((const float4*)(f0 + 24 * FI + k));
        float w0 = sW[(k + 0) * HD + c];
        float w1 = sW[(k + 1) * HD + c];
        float w2 = sW[(k + 2) * HD + c];
        float w3 = sW[(k + 3) * HD + c];
        a0 += fa.x * w0 + fa.y * w1 + fa.z * w2 + fa.w * w3;
        a1 += fb.x * w0 + fb.y * w1 + fb.z * w2 + fb.w * w3;
        a2 += fc.x * w0 + fc.y * w1 + fc.z * w2 + fc.w * w3;
        a3 += fd.x * w0 + fd.y * w1 + fd.z * w2 + fd.w * w3;
    }
    float* o = g_buf1 + row0 * HD;
    o[(rg) * HD + c] = a0;
    o[(rg + 8) * HD + c] = a1;
    o[(rg + 16) * HD + c] = a2;
    o[(rg + 24) * HD + c] = a3;
}

// ---------------------------------------------------------------------------
// Self-loop init: agg[i][:] = x[i][:] * dinv[i]^2
// DIR=0: x=g_buf1, agg=g_buf2.  DIR=1: x=g_buf2, agg=g_buf1.
// ---------------------------------------------------------------------------
template <int DIR>
__global__ void k_selfinit() {
    const float* x = DIR ? g_buf2 : g_buf1;
    float* agg = DIR ? g_buf1 : g_buf2;
    int i = blockIdx.x * blockDim.x + threadIdx.x;
    if (i < NN * HD) {
        float d = g_dinv[i >> 5];
        agg[i] = x[i] * d * d;
    }
}

// ---------------------------------------------------------------------------
// Edge scatter: one warp per edge, lane = feature.
// agg[dst][lane] += x[src][lane] * dinv[src]*dinv[dst]
// ---------------------------------------------------------------------------
template <int DIR>
__global__ void k_edge(const int* __restrict__ src, const int* __restrict__ dst) {
    const float* x = DIR ? g_buf2 : g_buf1;
    float* agg = DIR ? g_buf1 : g_buf2;
    int gt = blockIdx.x * blockDim.x + threadIdx.x;
    int e = gt >> 5;
    if (e >= NE) return;
    int lane = threadIdx.x & 31;
    int s = src[e];
    int d = dst[e];
    float nrm = g_dinv[s] * g_dinv[d];
    float v = x[s * HD + lane] * nrm;
    atomicAdd(&agg[d * HD + lane], v);
}

// ---------------------------------------------------------------------------
// out = relu(agg + b).  DIR=0: g_buf2 -> g_buf1.  DIR=1: g_buf1 -> g_buf2.
// ---------------------------------------------------------------------------
template <int DIR>
__global__ void k_biasrelu(const float* __restrict__ b) {
    const float* agg = DIR ? g_buf1 : g_buf2;
    float* out = DIR ? g_buf2 : g_buf1;
    int i = blockIdx.x * blockDim.x + threadIdx.x;
    if (i < NN * HD) out[i] = fmaxf(agg[i] + b[i & 31], 0.f);
}

// ---------------------------------------------------------------------------
// GEMM2: g_buf2 = g_buf1 @ W2   ([100k,32] x [32,32]), 64 rows per block
// ---------------------------------------------------------------------------
__global__ void __launch_bounds__(256) k_gemm2(const float* __restrict__ W2) {
    __shared__ float sW[HD * HD];   // 4KB
    __shared__ float sH[64 * 33];   // 8.25KB
    int t = threadIdx.x;
    for (int i = t; i < HD * HD; i += 256) sW[i] = W2[i];
    int row0 = blockIdx.x * 64;
    for (int i = t; i < 64 * 32; i += 256) {
        int r = i >> 5, c = i & 31;
        int gr = row0 + r;
        sH[r * 33 + c] = (gr < NN) ? g_buf1[gr * HD + c] : 0.f;
    }
    __syncthreads();
    int c = t & 31, rg = t >> 5;
    float acc[8];
#pragma unroll
    for (int i = 0; i < 8; i++) acc[i] = 0.f;
#pragma unroll
    for (int k = 0; k < HD; k++) {
        float w = sW[k * HD + c];
#pragma unroll
        for (int i = 0; i < 8; i++) acc[i] += sH[(rg + 8 * i) * 33 + k] * w;
    }
#pragma unroll
    for (int i = 0; i < 8; i++) {
        int gr = row0 + rg + 8 * i;
        if (gr < NN) g_buf2[gr * HD + c] = acc[i];
    }
}

// ---------------------------------------------------------------------------
// Fused heads, 16-node tile (static smem 41.3KB):
//   p1 = relu(h@pW1+pb1) [16,512] in SMEM  -> policy = p1@pW2+pb2 [16,64]
//   v1 = relu(h@vW1+vb1) [16,512] in SMEM  -> value  = v1@vW2+vb2 [16,1]
// h read from g_buf2.
// ---------------------------------------------------------------------------
__global__ void __launch_bounds__(256) k_head(
    const float* __restrict__ pW1, const float* __restrict__ pb1,
    const float* __restrict__ pW2, const float* __restrict__ pb2,
    const float* __restrict__ vW1, const float* __restrict__ vb1,
    const float* __restrict__ vW2, const float* __restrict__ vb2,
    float* __restrict__ out) {
    __shared__ float sH[16 * 33];   // 2112 floats
    __shared__ float sP[16 * 513];  // 8208 floats
    const int t = threadIdx.x;
    const int n0 = blockIdx.x * 16;

    for (int i = t; i < 16 * 32; i += 256) {
        int r = i >> 5, c = i & 31;
        sH[r * 33 + c] = g_buf2[(n0 + r) * HD + c];
    }
    __syncthreads();

    // ---- layer 1 (policy): sP = relu(h @ pW1 + pb1)
    {
        const int j0 = t, j1 = t + 256;
        float w0[32], w1[32];
#pragma unroll
        for (int k = 0; k < 32; k++) {
            w0[k] = __ldg(&pW1[k * PD + j0]);
            w1[k] = __ldg(&pW1[k * PD + j1]);
        }
        float bb0 = pb1[j0], bb1 = pb1[j1];
#pragma unroll 2
        for (int r = 0; r < 16; r++) {
            float s0 = bb0, s1 = bb1;
#pragma unroll
            for (int k = 0; k < 32; k++) {
                float hv = sH[r * 33 + k];
                s0 += hv * w0[k];
                s1 += hv * w1[k];
            }
            sP[r * 513 + j0] = fmaxf(s0, 0.f);
            sP[r * 513 + j1] = fmaxf(s1, 0.f);
        }
    }
    __syncthreads();

    // ---- layer 2 (policy): out = sP @ pW2 + pb2
    {
        int c = t & 31, rg = t >> 5;  // rows rg*2, rg*2+1
        float a0[2], a1[2];
        float bb0 = pb2[c], bb1 = pb2[c + 32];
#pragma unroll
        for (int i = 0; i < 2; i++) { a0[i] = bb0; a1[i] = bb1; }
#pragma unroll 4
        for (int k = 0; k < PD; k++) {
            float w0 = __ldg(&pW2[k * AD + c]);
            float w1 = __ldg(&pW2[k * AD + 32 + c]);
#pragma unroll
            for (int i = 0; i < 2; i++) {
                float p = sP[(rg * 2 + i) * 513 + k];
                a0[i] += p * w0;
                a1[i] += p * w1;
            }
        }
#pragma unroll
        for (int i = 0; i < 2; i++) {
            long long r = n0 + rg * 2 + i;
            out[r * AD + c] = a0[i];
            out[r * AD + 32 + c] = a1[i];
        }
    }
    __syncthreads();

    // ---- layer 1 (value): sP = relu(h @ vW1 + vb1)
    {
        const int j0 = t, j1 = t + 256;
        float w0[32], w1[32];
#pragma unroll
        for (int k = 0; k < 32; k++) {
            w0[k] = __ldg(&vW1[k * PD + j0]);
            w1[k] = __ldg(&vW1[k * PD + j1]);
        }
        float bb0 = vb1[j0], bb1 = vb1[j1];
#pragma unroll 2
        for (int r = 0; r < 16; r++) {
            float s0 = bb0, s1 = bb1;
#pragma unroll
            for (int k = 0; k < 32; k++) {
                float hv = sH[r * 33 + k];
                s0 += hv * w0[k];
                s1 += hv * w1[k];
            }
            sP[r * 513 + j0] = fmaxf(s0, 0.f);
            sP[r * 513 + j1] = fmaxf(s1, 0.f);
        }
    }
    __syncthreads();

    // ---- layer 2 (value): one thread per row; stride-513 -> conflict-free
    if (t < 16) {
        float s = vb2[0];
        for (int k = 0; k < PD; k++) s += sP[t * 513 + k] * __ldg(&vW2[k]);
        out[(long long)NN * AD + n0 + t] = s;
    }
}

// ---------------------------------------------------------------------------
// Host side: kernel launches ONLY.
// ---------------------------------------------------------------------------
extern "C" void kernel_launch(void* const* d_in, const int* in_sizes, int n_in,
                              void* d_out, int out_size) {
    const float* feat = (const float*)d_in[0];
    const int* ei = (const int*)d_in[1];  // int32! (JAX x64-off demotes int64)
    const float* W1 = (const float*)d_in[2];
    const float* b1 = (const float*)d_in[3];
    const float* W2 = (const float*)d_in[4];
    const float* b2 = (const float*)d_in[5];
    const float* pW1 = (const float*)d_in[6];
    const float* pb1 = (const float*)d_in[7];
    const float* pW2 = (const float*)d_in[8];
    const float* pb2 = (const float*)d_in[9];
    const float* vW1 = (const float*)d_in[10];
    const float* vb1 = (const float*)d_in[11];
    const float* vW2 = (const float*)d_in[12];
    const float* vb2 = (const float*)d_in[13];
    float* out = (float*)d_out;

    const int* src = ei;       // edge_index[0]
    const int* dst = ei + NE;  // edge_index[1]

    const int EB = (int)(((long long)NE * 32 + 255) / 256);

    k_zerodeg<<<(NN + 255) / 256, 256>>>();
    k_deg<<<(NE + 255) / 256, 256>>>(dst);
    k_dinv<<<(NN + 255) / 256, 256>>>();

    // conv1: buf1 = feat@W1 ; buf2 = aggregate ; buf1 = relu(buf2 + b1)
    k_gemm1<<<NN / 32, 256>>>(feat, W1);
    k_selfinit<0><<<(NN * HD + 255) / 256, 256>>>();
    k_edge<0><<<EB, 256>>>(src, dst);
    k_biasrelu<0><<<(NN * HD + 255) / 256, 256>>>(b1);

    // conv2: buf2 = buf1@W2 ; buf1 = aggregate ; buf2 = relu(buf1 + b2)
    k_gemm2<<<(NN + 63) / 64, 256>>>(W2);
    k_selfinit<1><<<(NN * HD + 255) / 256, 256>>>();
    k_edge<1><<<EB, 256>>>(src, dst);
    k_biasrelu<1><<<(NN * HD + 255) / 256, 256>>>(b2);

    // fused policy + value heads (reads g_buf2)
    k_head<<<NN / 16, 256>>>(pW1, pb1, pW2, pb2, vW1, vb1, vW2, vb2, out);
}